// round 16
// baseline (speedup 1.0000x reference)
#include <cuda_runtime.h>
#include <cstdint>

#define NPIX 262144      // 512*512
#define C64  64
#define LBL  8
#define NBLK 128         // hist blocks per side, 2048 px each
#define S2CHUNK 16
#define NSUB 4           // pixel subgroups in k_s2 (chunks written = S2CHUNK*NSUB)
#define APCHUNK 32
#define NSIT 4
#define PADPIX (NPIX + 512)
#define APS 268          // apply sX row stride (floats)
#define APSMEM (C64 * APS * 4 + C64 * C64 * 8 + 256)
#define NSS 66           // NS matrix smem stride

typedef unsigned long long ull;

// ---------------- static device scratch (allocations are forbidden) -------
__device__ int   g_blockcnt[2][NBLK][LBL];
__device__ int   g_boffA[2][LBL + 1];            // 64-aligned bucket starts
__device__ int   g_cnt[2][LBL];                  // actual bucket sizes
__device__ __align__(16) int   g_idx[2][PADPIX]; // bucket pos -> pixel index
__device__ __align__(16) int   g_pos[2][NPIX];   // pixel index -> bucket pos
__device__ __align__(16) float g_packed[2][C64][PADPIX];
__device__ float g_pS2[2][LBL][S2CHUNK * NSUB][C64 * C64];
__device__ float g_psum[2][LBL][S2CHUNK][C64];
__device__ float g_mu[2][LBL][C64];
__device__ float g_M[2][LBL][C64 * C64];  // side0: (cov_c+I)^-1/2, side1: cov_s^1/2
__device__ float g_T[LBL][C64 * C64];
__device__ float g_bias[LBL][C64];

// ---------------- packed f32x2 helpers ------------------------------------
__device__ __forceinline__ ull pk2(float lo, float hi) {
    ull r;
    asm("mov.b64 %0, {%1, %2};" : "=l"(r) : "f"(lo), "f"(hi));
    return r;
}
__device__ __forceinline__ void fma2(ull& d, ull a, ull b) {
    asm("fma.rn.f32x2 %0, %1, %2, %0;" : "+l"(d) : "l"(a), "l"(b));
}
__device__ __forceinline__ float2 upk(ull v) {
    float2 f;
    asm("mov.b64 {%0, %1}, %2;" : "=f"(f.x), "=f"(f.y) : "l"(v));
    return f;
}

// ---------------- 1. per-block label histograms ---------------------------
__global__ void k_hist(const int* __restrict__ cseg, const int* __restrict__ sseg) {
    int side = blockIdx.y;
    const int* seg = side ? sseg : cseg;
    int t = threadIdx.x;
    __shared__ int sc[LBL];
    if (t < LBL) sc[t] = 0;
    __syncthreads();
    int base = blockIdx.x * 2048 + t * 8;
    int lc[LBL] = {0, 0, 0, 0, 0, 0, 0, 0};
#pragma unroll
    for (int j = 0; j < 8; j++) { int l = seg[base + j] & 7; lc[l]++; }
#pragma unroll
    for (int l = 0; l < LBL; l++)
        if (lc[l]) atomicAdd(&sc[l], lc[l]);
    __syncthreads();
    if (t < LBL) g_blockcnt[side][blockIdx.x][t] = sc[t];
}

// ---------------- 2. scatter with inlined global scan + gap zeroing -------
__global__ void k_scatter(const int* __restrict__ cseg, const int* __restrict__ sseg) {
    int side = blockIdx.y;
    const int* seg = side ? sseg : cseg;
    int t = threadIdx.x, blk = blockIdx.x;
    __shared__ int pre[LBL][256];
    __shared__ int scnt[LBL];      // global per-label totals
    __shared__ int sbefore[LBL];   // per-label count in blocks < blk
    __shared__ int sboffA[LBL + 1];
    __shared__ int sbase[LBL];     // this block's run base per label

    int base = blk * 2048 + t * 8;
    int lab[8];
    int lc[LBL] = {0, 0, 0, 0, 0, 0, 0, 0};
#pragma unroll
    for (int j = 0; j < 8; j++) { lab[j] = seg[base + j] & 7; lc[lab[j]]++; }
#pragma unroll
    for (int l = 0; l < LBL; l++) pre[l][t] = lc[l];

    if (t < LBL) {  // redundant global scan (tiny, deterministic)
        int tot = 0, before = 0;
        for (int b = 0; b < NBLK; b++) {
            int c = g_blockcnt[side][b][t];
            if (b < blk) before += c;
            tot += c;
        }
        scnt[t] = tot;
        sbefore[t] = before;
    }
    __syncthreads();
    if (t < LBL) {
        int run = 0;
        for (int l2 = 0; l2 < t; l2++) run += (scnt[l2] + 63) & ~63;
        sboffA[t] = run;
        sbase[t] = run + sbefore[t];
        if (t == LBL - 1) sboffA[LBL] = run + ((scnt[t] + 63) & ~63);
        int r2 = 0;
        for (int i = 0; i < 256; i++) { int v = pre[t][i]; pre[t][i] = r2; r2 += v; }
    }
    __syncthreads();
    if (blk == 0 && t < LBL) {
        g_cnt[side][t] = scnt[t];
        g_boffA[side][t] = sboffA[t];
        if (t == 0) g_boffA[side][LBL] = sboffA[LBL];
    }
    int off[LBL];
#pragma unroll
    for (int l = 0; l < LBL; l++) off[l] = sbase[l] + pre[l][t];
#pragma unroll
    for (int j = 0; j < 8; j++) {
        int l = lab[j];
        int p = off[l]++;
        int i = base + j;
        g_idx[side][p] = i;
        g_pos[side][i] = p;
    }
    if (blk < LBL) {  // zero bucket alignment gaps
        int l = blk;
        int start = sboffA[l] + scnt[l];
        int gap = sboffA[l + 1] - start;
        int ch = t >> 2;
        for (int p = (t & 3); p < gap; p += 4)
            g_packed[side][ch][start + p] = 0.f;
    }
}

// ---------------- 3. pack features into bucket order ----------------------
__global__ void k_pack(const float* __restrict__ cont, const float* __restrict__ styl) {
    int side = blockIdx.y;
    const float4* X = (const float4*)(side ? styl : cont);
    int e = blockIdx.x * 256 + threadIdx.x;
    int c = e >> 16;
    int o4 = e & 65535;
    float4 v = X[(c << 16) + o4];
    int4 p = ((const int4*)g_pos[side])[o4];
    float* P = g_packed[side][c];
    P[p.x] = v.x; P[p.y] = v.y; P[p.z] = v.z; P[p.w] = v.w;
}

// ---------------- 4. raw second moments: 8x8 register tiles ---------------
// 4 subgroups of 64 threads split the pixel loop; each thread computes an
// 8x8 strided tile (r=rl+8i, c=cl+8j -> conflict-free LDS, 64 fma2 / 16 LDS).
// Double-buffered staging hides gmem latency. Partials: chunk = ck*NSUB+sub.
__global__ void __launch_bounds__(256, 1) k_s2() {
    int side = blockIdx.z, l = blockIdx.y, ck = blockIdx.x, t = threadIdx.x;
    __shared__ __align__(16) float sA[C64][66];
    __shared__ float ssum[C64][4];
    int b0 = g_boffA[side][l];
    int cnt = g_cnt[side][l];
    int nt = (cnt + 63) >> 6;
    int t0 = nt * ck / S2CHUNK, t1 = nt * (ck + 1) / S2CHUNK;
    int sub = t >> 6, tid64 = t & 63;
    int rl = tid64 >> 3, cl = tid64 & 7;
    ull acc[8][8];
#pragma unroll
    for (int i = 0; i < 8; i++)
#pragma unroll
        for (int j = 0; j < 8; j++) acc[i][j] = pk2(0.f, 0.f);
    int ch = t >> 2, po = (t & 3) * 16;
    const float* src = g_packed[side][ch];
    float csum = 0.f;
    int pb = b0 + t0 * 64, pe = b0 + t1 * 64;

    float4 v[4];
    if (pb < pe) {
#pragma unroll
        for (int k = 0; k < 4; k++) v[k] = *(const float4*)&src[pb + po + 4 * k];
    }
    for (; pb < pe; pb += 64) {
        // store staged regs (8B stores: row base 8B-aligned for any ch)
#pragma unroll
        for (int k = 0; k < 4; k++) {
            *(float2*)&sA[ch][po + 4 * k] = make_float2(v[k].x, v[k].y);
            *(float2*)&sA[ch][po + 4 * k + 2] = make_float2(v[k].z, v[k].w);
            csum += v[k].x + v[k].y + v[k].z + v[k].w;
        }
        __syncthreads();
        if (pb + 64 < pe) {  // prefetch next tile (overlaps compute)
#pragma unroll
            for (int k = 0; k < 4; k++) v[k] = *(const float4*)&src[pb + 64 + po + 4 * k];
        }
        int ppb = sub * 16;
#pragma unroll
        for (int q = 0; q < 8; q++) {
            int pp = ppb + 2 * q;
            ull ar[8], br[8];
#pragma unroll
            for (int i = 0; i < 8; i++) ar[i] = *(const ull*)&sA[rl + 8 * i][pp];
#pragma unroll
            for (int j = 0; j < 8; j++) br[j] = *(const ull*)&sA[cl + 8 * j][pp];
#pragma unroll
            for (int i = 0; i < 8; i++)
#pragma unroll
                for (int j = 0; j < 8; j++) fma2(acc[i][j], ar[i], br[j]);
        }
        __syncthreads();
    }
    float* dst = g_pS2[side][l][ck * NSUB + sub];
#pragma unroll
    for (int i = 0; i < 8; i++)
#pragma unroll
        for (int j = 0; j < 8; j++) {
            float2 f = upk(acc[i][j]);
            dst[(rl + 8 * i) * C64 + (cl + 8 * j)] = f.x + f.y;
        }
    ssum[ch][t & 3] = csum;
    __syncthreads();
    if (t < C64) {
        float s = ssum[t][0] + ssum[t][1] + ssum[t][2] + ssum[t][3];
        g_psum[side][l][ck][t] = s;
    }
}

// ---------------- 5. reduce + Newton-Schulz (fma2, symmetric reads) -------
__global__ void k_ns() {
    int l = blockIdx.x, side = blockIdx.y, t = threadIdx.x;
    __shared__ __align__(16) float sY[C64][NSS];
    __shared__ __align__(16) float sZ[C64][NSS];
    __shared__ __align__(16) float sT[C64][NSS];
    __shared__ float smu[C64];
    __shared__ float sred[C64];
    int n = g_cnt[side][l];
    float nF = (float)n;
    if (t < C64) {
        float s = 0.f;
        for (int ck = 0; ck < S2CHUNK; ck++) s += g_psum[side][l][ck][t];
        float mu = s / fmaxf(nF, 1.f);
        smu[t] = mu;
        g_mu[side][l][t] = mu;
    }
    __syncthreads();
    float div = (n == 1) ? 1e-5f : (nF - 1.f);  // n==0 -> -1, matching ref
#pragma unroll
    for (int i = 0; i < 16; i++) {
        int e = t * 16 + i;
        int r = e >> 6, c = e & 63;
        float s2 = 0.f;
        for (int ck = 0; ck < S2CHUNK * NSUB; ck++) s2 += g_pS2[side][l][ck][e];
        float cov = (s2 - nF * smu[r] * smu[c]) / div;
        if (side == 0 && r == c) cov += 1.f;
        sY[r][c] = cov;
    }
    __syncthreads();
    if (t < C64) {
        float rs = 0.f;
        for (int c = 0; c < C64; c++) rs += fabsf(sY[t][c]);
        sred[t] = rs;
    }
    __syncthreads();
    float s = 0.f;
    for (int i = 0; i < C64; i++) s = fmaxf(s, sred[i]);
    bool zero = (s < 1e-20f);
    if (zero) s = 1.f;
    float inv = 1.f / s;
    __syncthreads();
#pragma unroll
    for (int i = 0; i < 16; i++) {
        int e = t * 16 + i;
        int r = e >> 6, c = e & 63;
        sY[r][c] *= inv;
        sZ[r][c] = (r == c) ? 1.f : 0.f;
    }
    int r0 = (t >> 4) << 2, c0 = (t & 15) << 2;
    for (int it = 0; it < NSIT; it++) {
        __syncthreads();
        ull a2[4][4];
#pragma unroll
        for (int i = 0; i < 4; i++)
#pragma unroll
            for (int j = 0; j < 4; j++) a2[i][j] = pk2(0.f, 0.f);
        for (int kk = 0; kk < C64; kk += 2) {
            ull zr[4], yc[4];
#pragma unroll
            for (int i = 0; i < 4; i++) zr[i] = *(const ull*)&sZ[r0 + i][kk];
#pragma unroll
            for (int j = 0; j < 4; j++) yc[j] = *(const ull*)&sY[c0 + j][kk];
#pragma unroll
            for (int i = 0; i < 4; i++)
#pragma unroll
                for (int j = 0; j < 4; j++) fma2(a2[i][j], zr[i], yc[j]);
        }
#pragma unroll
        for (int i = 0; i < 4; i++)
#pragma unroll
            for (int j = 0; j < 4; j++) {
                float2 f = upk(a2[i][j]);
                float v = -0.5f * (f.x + f.y);
                if (r0 + i == c0 + j) v += 1.5f;
                sT[r0 + i][c0 + j] = v;
            }
        __syncthreads();
        ull ay[4][4], az[4][4];
#pragma unroll
        for (int i = 0; i < 4; i++)
#pragma unroll
            for (int j = 0; j < 4; j++) { ay[i][j] = pk2(0.f, 0.f); az[i][j] = pk2(0.f, 0.f); }
        for (int kk = 0; kk < C64; kk += 2) {
            ull yr[4], tr[4], tc[4], zc[4];
#pragma unroll
            for (int i = 0; i < 4; i++) {
                yr[i] = *(const ull*)&sY[r0 + i][kk];
                tr[i] = *(const ull*)&sT[r0 + i][kk];
            }
#pragma unroll
            for (int j = 0; j < 4; j++) {
                tc[j] = *(const ull*)&sT[c0 + j][kk];
                zc[j] = *(const ull*)&sZ[c0 + j][kk];
            }
#pragma unroll
            for (int i = 0; i < 4; i++)
#pragma unroll
                for (int j = 0; j < 4; j++) {
                    fma2(ay[i][j], yr[i], tc[j]);
                    fma2(az[i][j], tr[i], zc[j]);
                }
        }
        __syncthreads();
#pragma unroll
        for (int i = 0; i < 4; i++)
#pragma unroll
            for (int j = 0; j < 4; j++) {
                float2 fy = upk(ay[i][j]);
                float2 fz = upk(az[i][j]);
                sY[r0 + i][c0 + j] = fy.x + fy.y;
                sZ[r0 + i][c0 + j] = fz.x + fz.y;
            }
    }
    __syncthreads();
    float fac = zero ? 0.f : (side == 0 ? (1.f / sqrtf(s)) : sqrtf(s));
    float* M = g_M[side][l];
#pragma unroll
    for (int i = 0; i < 4; i++)
#pragma unroll
        for (int j = 0; j < 4; j++) {
            float v = (side == 0 ? sZ[r0 + i][c0 + j] : sY[r0 + i][c0 + j]) * fac;
            M[(r0 + i) * C64 + (c0 + j)] = v;
        }
}

// ---------------- 6. T = Co @ Wh (fma2, Wh sym), bias, validity -----------
__global__ void k_t() {
    int l = blockIdx.x, t = threadIdx.x;
    __shared__ __align__(16) float sW[C64][NSS];
    __shared__ __align__(16) float sC[C64][NSS];
#pragma unroll
    for (int i = 0; i < 16; i++) {
        int e = t * 16 + i;
        int r = e >> 6, c = e & 63;
        sW[r][c] = g_M[0][l][e];
        sC[r][c] = g_M[1][l][e];
    }
    __syncthreads();
    float ncF = (float)g_cnt[0][l], nsF = (float)g_cnt[1][l];
    bool valid = (ncF > 10.f) && (nsF > 10.f) && (ncF < 100.f * nsF) && (nsF < 100.f * ncF);
    int r0 = (t >> 4) << 2, c0 = (t & 15) << 2;
    ull a2[4][4];
#pragma unroll
    for (int i = 0; i < 4; i++)
#pragma unroll
        for (int j = 0; j < 4; j++) a2[i][j] = pk2(0.f, 0.f);
    for (int kk = 0; kk < C64; kk += 2) {
        ull cr[4], wr[4];
#pragma unroll
        for (int i = 0; i < 4; i++) cr[i] = *(const ull*)&sC[r0 + i][kk];
#pragma unroll
        for (int j = 0; j < 4; j++) wr[j] = *(const ull*)&sW[c0 + j][kk];
#pragma unroll
        for (int i = 0; i < 4; i++)
#pragma unroll
            for (int j = 0; j < 4; j++) fma2(a2[i][j], cr[i], wr[j]);
    }
    float tt[4][4];
#pragma unroll
    for (int i = 0; i < 4; i++)
#pragma unroll
        for (int j = 0; j < 4; j++) {
            float2 f = upk(a2[i][j]);
            tt[i][j] = valid ? (f.x + f.y) : ((r0 + i == c0 + j) ? 1.f : 0.f);
        }
    __syncthreads();
#pragma unroll
    for (int i = 0; i < 4; i++)
#pragma unroll
        for (int j = 0; j < 4; j++) {
            sW[r0 + i][c0 + j] = tt[i][j];
            g_T[l][(r0 + i) * C64 + (c0 + j)] = tt[i][j];
        }
    __syncthreads();
    if (t < C64) {
        float b = 0.f;
        for (int c = 0; c < C64; c++) b = fmaf(sW[t][c], g_mu[0][l][c], b);
        g_bias[l][t] = valid ? (g_mu[1][l][t] - b) : 0.f;
    }
}

// ---------------- 7. apply Y = T X + b: 8 rows x 4 pairs per thread -------
// Warp-uniform row group (rl = warp id) -> all T loads are broadcasts.
__global__ void k_apply(float* __restrict__ out) {
    extern __shared__ __align__(16) char apbuf[];
    float (*sX)[APS] = (float(*)[APS])apbuf;
    ull (*sTd)[C64] = (ull(*)[C64])(apbuf + C64 * APS * 4);
    float* sb = (float*)(apbuf + C64 * APS * 4 + C64 * C64 * 8);

    int l = blockIdx.y, ck = blockIdx.x, t = threadIdx.x;
    int lane = t & 31, wrp = t >> 5;   // wrp = row-group base
    int b0 = g_boffA[0][l];
    int cnt = g_cnt[0][l];
    int ae = b0 + cnt;
    int nt = (cnt + 255) >> 8;
    int t0 = nt * ck / APCHUNK, t1 = nt * (ck + 1) / APCHUNK;

#pragma unroll
    for (int i = 0; i < 16; i++) {     // duplicated transposed T
        int e = t * 16 + i;
        float v = g_T[l][e];
        sTd[e & 63][e >> 6] = pk2(v, v);
    }
    if (t < C64) sb[t] = g_bias[l][t];
    __syncthreads();
    float bb[8];
#pragma unroll
    for (int i = 0; i < 8; i++) bb[i] = sb[wrp + 8 * i];

    for (int pb = b0 + t0 * 256; pb < b0 + t1 * 256; pb += 256) {
#pragma unroll
        for (int half = 0; half < 2; half++) {
            int ch = (t >> 3) + (half << 5);
            const float* src = g_packed[0][ch];
            float* drow = sX[ch];
            int po = (t & 7) * 4;
#pragma unroll
            for (int k = 0; k < 8; k++) {
                float4 v = *(const float4*)&src[pb + po + 32 * k];
                *(float4*)&drow[po + 32 * k] = v;
            }
        }
        __syncthreads();

        ull acc[8][4];
#pragma unroll
        for (int i = 0; i < 8; i++)
#pragma unroll
            for (int m = 0; m < 4; m++) acc[i][m] = pk2(0.f, 0.f);
#pragma unroll 4
        for (int c = 0; c < C64; c++) {
            const float* xr = sX[c];
            ull xm[4];
#pragma unroll
            for (int m = 0; m < 4; m++) xm[m] = *(const ull*)&xr[2 * lane + 64 * m];
            ull td[8];
#pragma unroll
            for (int i = 0; i < 8; i++) td[i] = sTd[c][wrp + 8 * i];  // broadcast
#pragma unroll
            for (int i = 0; i < 8; i++)
#pragma unroll
                for (int m = 0; m < 4; m++) fma2(acc[i][m], td[i], xm[m]);
        }
#pragma unroll
        for (int m = 0; m < 4; m++) {
            int p0 = pb + 2 * lane + 64 * m;
            bool v0 = p0 < ae, v1 = p0 + 1 < ae;
            int i0 = v0 ? g_idx[0][p0] : 0;
            int i1 = v1 ? g_idx[0][p0 + 1] : 0;
#pragma unroll
            for (int i = 0; i < 8; i++) {
                float2 f = upk(acc[i][m]);
                int r = wrp + 8 * i;
                long long rowb = (long long)r * NPIX;
                if (v0) out[rowb + i0] = f.x + bb[i];
                if (v1) out[rowb + i1] = f.y + bb[i];
            }
        }
        __syncthreads();
    }
}

// ---------------- launch ---------------------------------------------------
extern "C" void kernel_launch(void* const* d_in, const int* in_sizes, int n_in,
                              void* d_out, int out_size) {
    (void)in_sizes; (void)n_in; (void)out_size;
    const float* cont = (const float*)d_in[0];
    const float* styl = (const float*)d_in[1];
    const int* cseg = (const int*)d_in[2];
    const int* sseg = (const int*)d_in[3];
    float* out = (float*)d_out;

    cudaFuncSetAttribute(k_apply, cudaFuncAttributeMaxDynamicSharedMemorySize, APSMEM);

    k_hist<<<dim3(NBLK, 2), 256>>>(cseg, sseg);
    k_scatter<<<dim3(NBLK, 2), 256>>>(cseg, sseg);
    k_pack<<<dim3((C64 * NPIX / 4) / 256, 2), 256>>>(cont, styl);
    k_s2<<<dim3(S2CHUNK, LBL, 2), 256>>>();           // 4th launch -> profiled
    k_ns<<<dim3(LBL, 2), 256>>>();
    k_t<<<LBL, 256>>>();
    k_apply<<<dim3(APCHUNK, LBL), 256, APSMEM>>>(out);
}